// round 1
// baseline (speedup 1.0000x reference)
#include <cuda_runtime.h>

// ---------------------------------------------------------------------------
// GraphConvDistanceLayer:
//   out[i] = sum_{e: w_rows[e]==i} Param_W[w_params[e]] * x[w_cols[e]]
//            + Param_b[b_params[i]]
//
// N = 262144 outputs, E = 16.7M edges.
// Strategy: init out with bias, then atomic scatter over edges.
// x (1MB) and out (1MB) are L2-resident; the only HBM traffic is the three
// coalesced index streams (201 MB total).
// ---------------------------------------------------------------------------

__global__ void bias_init_kernel(const float* __restrict__ Param_b,
                                 const int*   __restrict__ b_params,
                                 float*       __restrict__ out,
                                 int N)
{
    int i = blockIdx.x * blockDim.x + threadIdx.x;
    if (i < N) {
        out[i] = __ldg(&Param_b[b_params[i]]);
    }
}

__global__ void edge_scatter_vec4_kernel(const float* __restrict__ x,
                                         const float* __restrict__ Param_W,
                                         const int4*  __restrict__ rows4,
                                         const int4*  __restrict__ cols4,
                                         const int4*  __restrict__ params4,
                                         float*       __restrict__ out,
                                         int E4)
{
    int t = blockIdx.x * blockDim.x + threadIdx.x;
    if (t >= E4) return;

    // Three coalesced 16B loads -> 12 ints describing 4 edges. Front-batched
    // for MLP so the long-scoreboard waits overlap.
    int4 r = rows4[t];
    int4 c = cols4[t];
    int4 p = params4[t];

    // Gathers: Param_W is tiny (L1-hot), x is 1MB (L2-hot).
    float v0 = __ldg(&Param_W[p.x]) * __ldg(&x[c.x]);
    float v1 = __ldg(&Param_W[p.y]) * __ldg(&x[c.y]);
    float v2 = __ldg(&Param_W[p.z]) * __ldg(&x[c.z]);
    float v3 = __ldg(&Param_W[p.w]) * __ldg(&x[c.w]);

    // No-return atomics -> RED.ADD.F32 at L2.
    atomicAdd(&out[r.x], v0);
    atomicAdd(&out[r.y], v1);
    atomicAdd(&out[r.z], v2);
    atomicAdd(&out[r.w], v3);
}

// Scalar tail for E not divisible by 4 (not expected here, but safe).
__global__ void edge_scatter_tail_kernel(const float* __restrict__ x,
                                         const float* __restrict__ Param_W,
                                         const int*   __restrict__ rows,
                                         const int*   __restrict__ cols,
                                         const int*   __restrict__ params,
                                         float*       __restrict__ out,
                                         int start, int E)
{
    int e = start + blockIdx.x * blockDim.x + threadIdx.x;
    if (e < E) {
        float v = __ldg(&Param_W[params[e]]) * __ldg(&x[cols[e]]);
        atomicAdd(&out[rows[e]], v);
    }
}

extern "C" void kernel_launch(void* const* d_in, const int* in_sizes, int n_in,
                              void* d_out, int out_size)
{
    // metadata order: x, Param_W, Param_b, w_rows, w_cols, w_params, b_params
    const float* x        = (const float*)d_in[0];
    const float* Param_W  = (const float*)d_in[1];
    const float* Param_b  = (const float*)d_in[2];
    const int*   w_rows   = (const int*)  d_in[3];
    const int*   w_cols   = (const int*)  d_in[4];
    const int*   w_params = (const int*)  d_in[5];
    const int*   b_params = (const int*)  d_in[6];
    float*       out      = (float*)d_out;

    const int N = out_size;        // 262144
    const int E = in_sizes[3];     // 16777216

    // 1) Initialize output with gathered bias (also clears the 0xAA poison).
    {
        int threads = 256;
        int blocks  = (N + threads - 1) / threads;
        bias_init_kernel<<<blocks, threads>>>(Param_b, b_params, out, N);
    }

    // 2) Edge scatter, 4 edges per thread via int4 index loads.
    {
        int E4 = E / 4;
        if (E4 > 0) {
            int threads = 256;
            int blocks  = (E4 + threads - 1) / threads;
            edge_scatter_vec4_kernel<<<blocks, threads>>>(
                x, Param_W,
                (const int4*)w_rows, (const int4*)w_cols, (const int4*)w_params,
                out, E4);
        }
        int tail_start = E4 * 4;
        int tail = E - tail_start;
        if (tail > 0) {
            edge_scatter_tail_kernel<<<1, 256>>>(
                x, Param_W, w_rows, w_cols, w_params, out, tail_start, E);
        }
    }
}